// round 9
// baseline (speedup 1.0000x reference)
#include <cuda_runtime.h>
#include <cuda_fp16.h>
#include <cstdint>
#include <cstddef>

#define KDIM 4096
#define NDIM 11008
#define MMAX 8192
#define BM 128
#define BN 256
#define BK 64
#define ROWH (BK + 8)                  // 72 halfs = 144 B padded row (16B-multiple pad)
#define ATILE_B (BM * ROWH * 2)        // 18432
#define BTILE_B (BN * ROWH * 2)        // 36864
#define STAGE_B (ATILE_B + BTILE_B)    // 55296
#define SMEM_BYTES (2 * STAGE_B)       // 110592

#define DQ_BLOCKS ((NDIM / 64) * (KDIM / 64))   // 11008

// Static device scratch (no dynamic allocation allowed)
__device__ __half g_Xh[(size_t)MMAX * KDIM];   // x as fp16, [M, K]
__device__ __half g_Wt[(size_t)NDIM * KDIM];   // dequantized W, transposed: [N, K]

// ---------------- helpers ----------------
__device__ __forceinline__ uint32_t smem_u32(const void* p) {
    uint32_t a;
    asm("{ .reg .u64 t; cvta.to.shared.u64 t, %1; cvt.u32.u64 %0, t; }" : "=r"(a) : "l"(p));
    return a;
}

__device__ __forceinline__ void cp16(uint32_t sdst, const void* gsrc) {
    asm volatile("cp.async.cg.shared.global [%0], [%1], 16;" :: "r"(sdst), "l"(gsrc));
}

__device__ __forceinline__ void ldm_x4(uint32_t* r, uint32_t addr) {
    asm volatile("ldmatrix.sync.aligned.m8n8.x4.shared.b16 {%0,%1,%2,%3}, [%4];"
                 : "=r"(r[0]), "=r"(r[1]), "=r"(r[2]), "=r"(r[3]) : "r"(addr));
}

// fp16-accumulator MMA
__device__ __forceinline__ void mma_h(uint32_t& c0, uint32_t& c1,
                                      const uint32_t* a, uint32_t b0, uint32_t b1) {
    asm volatile("mma.sync.aligned.m16n8k16.row.col.f16.f16.f16.f16 "
                 "{%0,%1}, {%2,%3,%4,%5}, {%6,%7}, {%0,%1};"
                 : "+r"(c0), "+r"(c1)
                 : "r"(a[0]), "r"(a[1]), "r"(a[2]), "r"(a[3]), "r"(b0), "r"(b1));
}

// ---------------- Kernel 1: fused prep (dequant W + convert x) ----------------
__global__ void __launch_bounds__(256)
prep_kernel(const float* __restrict__ x, long long n8,
            const int* __restrict__ qweight,
            const float* __restrict__ scales,
            const int* __restrict__ qzeros) {
    __shared__ __half s[64][72];
    const int b = blockIdx.x;
    const int t = threadIdx.x;

    if (b < DQ_BLOCKS) {
        const int n0 = (b % (NDIM / 64)) * 64;
        const int k0 = (b / (NDIM / 64)) * 64;
        const int g  = k0 >> 7;

        const int nl = t & 63;
        const int n  = n0 + nl;
        const uint32_t zq =
            ((uint32_t)qzeros[(size_t)g * (NDIM / 8) + (n >> 3)] >> ((n & 7) * 4)) & 15u;
        const float z  = (float)(zq + 1u);
        const float sc = scales[(size_t)g * NDIM + n];

#pragma unroll
        for (int p = 0; p < 2; ++p) {
            const int kpl = (t >> 6) + 4 * p;
            const uint32_t qw = (uint32_t)qweight[(size_t)(k0 / 8 + kpl) * NDIM + n];
            union { uint4 u; __half h[8]; } v;
#pragma unroll
            for (int j = 0; j < 8; ++j) {
                float q = (float)((qw >> (4 * j)) & 15u);
                v.h[j] = __float2half_rn((q - z) * sc);
            }
            *reinterpret_cast<uint4*>(&s[nl][kpl * 8]) = v.u;
        }
        __syncthreads();

        const int rn = t >> 2, c = t & 3;
        uint4 v0 = *reinterpret_cast<const uint4*>(&s[rn][c * 16]);
        uint4 v1 = *reinterpret_cast<const uint4*>(&s[rn][c * 16 + 8]);
        __half* dst = &g_Wt[(size_t)(n0 + rn) * KDIM + k0 + c * 16];
        *reinterpret_cast<uint4*>(dst)     = v0;
        *reinterpret_cast<uint4*>(dst + 8) = v1;
    } else {
        const long long gid = (long long)(b - DQ_BLOCKS) * 256 + t;
        if (gid < n8) {
            const long long i4 = gid * 2;
            float4 v0 = reinterpret_cast<const float4*>(x)[i4];
            float4 v1 = reinterpret_cast<const float4*>(x)[i4 + 1];
            __half2* dst = reinterpret_cast<__half2*>(g_Xh) + i4 * 2;
            dst[0] = __floats2half2_rn(v0.x, v0.y);
            dst[1] = __floats2half2_rn(v0.z, v0.w);
            dst[2] = __floats2half2_rn(v1.x, v1.y);
            dst[3] = __floats2half2_rn(v1.z, v1.w);
        }
    }
}

// ---------------- Kernel 2: fp16-accum GEMM, CTA 128x256, warp tile 64x64 ----------------
// 8 warps (2m x 4n), BK=64, 2-stage. B fragments loaded one x4 at a time (low reg pressure).
__global__ void __launch_bounds__(256, 1)
gemm_kernel(const float* __restrict__ bias, float* __restrict__ out) {
    extern __shared__ char dsm[];
    const uint32_t sbase = smem_u32(dsm);          // stage s: A at s*STAGE_B, B at +ATILE_B

    const int tid  = threadIdx.x;
    const int lane = tid & 31;
    const int wid  = tid >> 5;
    const int warp_m = wid & 1;       // 2 -> 64 rows each
    const int warp_n = wid >> 1;      // 4 -> 64 cols each

    // grouped rasterization along M (B-tile reuse in L2)
    const int PN = gridDim.x, PM = gridDim.y;
    const int bid = blockIdx.y * PN + blockIdx.x;
    const int GM = 16;
    const int npg = GM * PN;
    const int fm  = (bid / npg) * GM;
    const int gsm = (PM - fm < GM) ? (PM - fm) : GM;
    const int pm  = fm + (bid % gsm);
    const int pn  = (bid % npg) / gsm;
    const int m0 = pm * BM;
    const int n0 = pn * BN;

    const __half* Ag = g_Xh + (size_t)m0 * KDIM;
    const __half* Bg = g_Wt + (size_t)n0 * KDIM;

    const int c8 = tid & 7;
    const int r0 = tid >> 3;          // 0..31

    float    accf[4][8][4];
    uint32_t hacc[4][8][2];
#pragma unroll
    for (int i = 0; i < 4; ++i)
#pragma unroll
        for (int j = 0; j < 8; ++j) {
            accf[i][j][0] = accf[i][j][1] = accf[i][j][2] = accf[i][j][3] = 0.f;
            hacc[i][j][0] = hacc[i][j][1] = 0u;
        }

    const int a_r = warp_m * 64 + (lane & 15);
    const int a_c = (lane >> 4) * 8;
    const int b_r = warp_n * 64 + ((lane >> 4) * 8) + (lane & 7);
    const int b_c = ((lane >> 3) & 1) * 8;

    const int NIT = KDIM / BK;        // 64

    // prologue: stage 0
    {
        const uint32_t sa  = sbase;
        const uint32_t sbb = sbase + ATILE_B;
#pragma unroll
        for (int p = 0; p < 4; ++p) {
            const int row = r0 + p * 32;
            cp16(sa + (uint32_t)(row * ROWH + c8 * 8) * 2, Ag + (size_t)row * KDIM + c8 * 8);
        }
#pragma unroll
        for (int p = 0; p < 8; ++p) {
            const int row = r0 + p * 32;
            cp16(sbb + (uint32_t)(row * ROWH + c8 * 8) * 2, Bg + (size_t)row * KDIM + c8 * 8);
        }
        asm volatile("cp.async.commit_group;" ::: "memory");
    }

#pragma unroll 1
    for (int it = 0; it < NIT; ++it) {
        asm volatile("cp.async.wait_group 0;" ::: "memory");
        __syncthreads();

        if (it + 1 < NIT) {
            const int st = (it + 1) & 1;
            const int k0 = (it + 1) * BK;
            const uint32_t sa  = sbase + st * STAGE_B;
            const uint32_t sbb = sa + ATILE_B;
#pragma unroll
            for (int p = 0; p < 4; ++p) {
                const int row = r0 + p * 32;
                cp16(sa + (uint32_t)(row * ROWH + c8 * 8) * 2,
                     Ag + (size_t)row * KDIM + k0 + c8 * 8);
            }
#pragma unroll
            for (int p = 0; p < 8; ++p) {
                const int row = r0 + p * 32;
                cp16(sbb + (uint32_t)(row * ROWH + c8 * 8) * 2,
                     Bg + (size_t)row * KDIM + k0 + c8 * 8);
            }
        }
        asm volatile("cp.async.commit_group;" ::: "memory");

        const int st = it & 1;
        const uint32_t sa  = sbase + st * STAGE_B;
        const uint32_t sbb = sa + ATILE_B;
#pragma unroll
        for (int ks = 0; ks < 4; ++ks) {
            const int kh = ks * 16;
            uint32_t Af[4][4];
#pragma unroll
            for (int mi = 0; mi < 4; ++mi)
                ldm_x4(Af[mi], sa + (uint32_t)(((a_r + mi * 16) * ROWH) + kh + a_c) * 2);
            // B fragments: ONE ldmatrix.x4 (4 regs) at a time, consumed immediately.
#pragma unroll
            for (int nj = 0; nj < 4; ++nj) {
                uint32_t Bf[4];
                ldm_x4(Bf, sbb + (uint32_t)(((b_r + nj * 16) * ROWH) + kh + b_c) * 2);
#pragma unroll
                for (int mi = 0; mi < 4; ++mi) {
                    mma_h(hacc[mi][2 * nj][0],     hacc[mi][2 * nj][1],
                          Af[mi], Bf[0], Bf[1]);
                    mma_h(hacc[mi][2 * nj + 1][0], hacc[mi][2 * nj + 1][1],
                          Af[mi], Bf[2], Bf[3]);
                }
            }
        }

        // promote fp16 chunk accumulators to fp32 every 2 iters (128 k)
        if (it & 1) {
#pragma unroll
            for (int mi = 0; mi < 4; ++mi)
#pragma unroll
                for (int ni = 0; ni < 8; ++ni) {
                    float2 lo = __half22float2(*reinterpret_cast<__half2*>(&hacc[mi][ni][0]));
                    float2 hi = __half22float2(*reinterpret_cast<__half2*>(&hacc[mi][ni][1]));
                    accf[mi][ni][0] += lo.x;
                    accf[mi][ni][1] += lo.y;
                    accf[mi][ni][2] += hi.x;
                    accf[mi][ni][3] += hi.y;
                    hacc[mi][ni][0] = 0u;
                    hacc[mi][ni][1] = 0u;
                }
        }
    }

    // epilogue: bias + store
    const int r  = lane >> 2;
    const int c2 = (lane & 3) * 2;
    const int orow0 = m0 + warp_m * 64;
    const int ocol0 = n0 + warp_n * 64;
#pragma unroll
    for (int ni = 0; ni < 8; ++ni) {
        const int ncol = ocol0 + ni * 8 + c2;
        const float b0 = bias[ncol], b1 = bias[ncol + 1];
#pragma unroll
        for (int mi = 0; mi < 4; ++mi) {
            const int mrow = orow0 + mi * 16 + r;
            float2 v0 = { accf[mi][ni][0] + b0, accf[mi][ni][1] + b1 };
            float2 v1 = { accf[mi][ni][2] + b0, accf[mi][ni][3] + b1 };
            *reinterpret_cast<float2*>(out + (size_t)mrow * NDIM + ncol)       = v0;
            *reinterpret_cast<float2*>(out + (size_t)(mrow + 8) * NDIM + ncol) = v1;
        }
    }
}

// ---------------- Launch ----------------
extern "C" void kernel_launch(void* const* d_in, const int* in_sizes, int n_in,
                              void* d_out, int out_size) {
    const float* x       = (const float*)d_in[0];
    const int*   qweight = (const int*)d_in[1];
    const float* scales  = (const float*)d_in[2];
    const int*   qzeros  = (const int*)d_in[3];
    const float* bias    = (const float*)d_in[4];
    float* out = (float*)d_out;

    const long long xsz = (long long)in_sizes[0];
    const int M = (int)(xsz / KDIM);          // 8192

    const long long n8 = xsz / 8;
    const int cv_blocks = (int)((n8 + 255) / 256);
    prep_kernel<<<DQ_BLOCKS + cv_blocks, 256>>>(x, n8, qweight, scales, qzeros);

    cudaFuncSetAttribute(gemm_kernel, cudaFuncAttributeMaxDynamicSharedMemorySize, SMEM_BYTES);
    gemm_kernel<<<dim3(NDIM / BN, M / BM), 256, SMEM_BYTES>>>(bias, out);
}

// round 10
// speedup vs baseline: 1.0803x; 1.0803x over previous
#include <cuda_runtime.h>
#include <cuda_fp16.h>
#include <cstdint>
#include <cstddef>

#define KDIM 4096
#define NDIM 11008
#define MMAX 8192
#define BM 128
#define BN 256
#define BK 64
#define ROWH (BK + 8)                  // 72 halfs = 144 B padded row
#define ATILE_B (BM * ROWH * 2)        // 18432
#define BTILE_B (BN * ROWH * 2)        // 36864
#define STAGE_B (ATILE_B + BTILE_B)    // 55296
#define SMEM_BYTES (2 * STAGE_B)       // 110592

#define DQ_BLOCKS ((NDIM / 64) * (KDIM / 64))   // 11008

// Static device scratch (no dynamic allocation allowed)
__device__ __half g_Xh[(size_t)MMAX * KDIM];   // x as fp16, [M, K]
__device__ __half g_Wt[(size_t)NDIM * KDIM];   // dequantized W, transposed: [N, K]

// ---------------- helpers ----------------
__device__ __forceinline__ uint32_t smem_u32(const void* p) {
    uint32_t a;
    asm("{ .reg .u64 t; cvta.to.shared.u64 t, %1; cvt.u32.u64 %0, t; }" : "=r"(a) : "l"(p));
    return a;
}

__device__ __forceinline__ void cp16(uint32_t sdst, const void* gsrc) {
    asm volatile("cp.async.cg.shared.global [%0], [%1], 16;" :: "r"(sdst), "l"(gsrc));
}

__device__ __forceinline__ void ldm_x4(uint32_t* r, uint32_t addr) {
    asm volatile("ldmatrix.sync.aligned.m8n8.x4.shared.b16 {%0,%1,%2,%3}, [%4];"
                 : "=r"(r[0]), "=r"(r[1]), "=r"(r[2]), "=r"(r[3]) : "r"(addr));
}

// fp32-accumulator MMA (in-place accumulate; no shadow registers needed)
__device__ __forceinline__ void mma_f(float* c, const uint32_t* a, uint32_t b0, uint32_t b1) {
    asm volatile("mma.sync.aligned.m16n8k16.row.col.f32.f16.f16.f32 "
                 "{%0,%1,%2,%3}, {%4,%5,%6,%7}, {%8,%9}, {%0,%1,%2,%3};"
                 : "+f"(c[0]), "+f"(c[1]), "+f"(c[2]), "+f"(c[3])
                 : "r"(a[0]), "r"(a[1]), "r"(a[2]), "r"(a[3]), "r"(b0), "r"(b1));
}

// ---------------- Kernel 1: fused prep (dequant W + convert x) ----------------
__global__ void __launch_bounds__(256)
prep_kernel(const float* __restrict__ x, long long n8,
            const int* __restrict__ qweight,
            const float* __restrict__ scales,
            const int* __restrict__ qzeros) {
    __shared__ __half s[64][72];
    const int b = blockIdx.x;
    const int t = threadIdx.x;

    if (b < DQ_BLOCKS) {
        const int n0 = (b % (NDIM / 64)) * 64;
        const int k0 = (b / (NDIM / 64)) * 64;
        const int g  = k0 >> 7;

        const int nl = t & 63;
        const int n  = n0 + nl;
        const uint32_t zq =
            ((uint32_t)qzeros[(size_t)g * (NDIM / 8) + (n >> 3)] >> ((n & 7) * 4)) & 15u;
        const float z  = (float)(zq + 1u);
        const float sc = scales[(size_t)g * NDIM + n];

#pragma unroll
        for (int p = 0; p < 2; ++p) {
            const int kpl = (t >> 6) + 4 * p;
            const uint32_t qw = (uint32_t)qweight[(size_t)(k0 / 8 + kpl) * NDIM + n];
            union { uint4 u; __half h[8]; } v;
#pragma unroll
            for (int j = 0; j < 8; ++j) {
                float q = (float)((qw >> (4 * j)) & 15u);
                v.h[j] = __float2half_rn((q - z) * sc);
            }
            *reinterpret_cast<uint4*>(&s[nl][kpl * 8]) = v.u;
        }
        __syncthreads();

        const int rn = t >> 2, c = t & 3;
        uint4 v0 = *reinterpret_cast<const uint4*>(&s[rn][c * 16]);
        uint4 v1 = *reinterpret_cast<const uint4*>(&s[rn][c * 16 + 8]);
        __half* dst = &g_Wt[(size_t)(n0 + rn) * KDIM + k0 + c * 16];
        *reinterpret_cast<uint4*>(dst)     = v0;
        *reinterpret_cast<uint4*>(dst + 8) = v1;
    } else {
        const long long gid = (long long)(b - DQ_BLOCKS) * 256 + t;
        if (gid < n8) {
            const long long i4 = gid * 2;
            float4 v0 = reinterpret_cast<const float4*>(x)[i4];
            float4 v1 = reinterpret_cast<const float4*>(x)[i4 + 1];
            __half2* dst = reinterpret_cast<__half2*>(g_Xh) + i4 * 2;
            dst[0] = __floats2half2_rn(v0.x, v0.y);
            dst[1] = __floats2half2_rn(v0.z, v0.w);
            dst[2] = __floats2half2_rn(v1.x, v1.y);
            dst[3] = __floats2half2_rn(v1.z, v1.w);
        }
    }
}

// ---------------- Kernel 2: fp32-accum GEMM, CTA 128x256, warp tile 64x64 ----------------
// 8 warps (2m x 4n), BK=64, 2-stage. No shadow accumulators -> ~185 regs, no spills.
__global__ void __launch_bounds__(256, 1)
gemm_kernel(const float* __restrict__ bias, float* __restrict__ out) {
    extern __shared__ char dsm[];
    const uint32_t sbase = smem_u32(dsm);          // stage s: A at s*STAGE_B, B at +ATILE_B

    const int tid  = threadIdx.x;
    const int lane = tid & 31;
    const int wid  = tid >> 5;
    const int warp_m = wid & 1;       // 2 -> 64 rows each
    const int warp_n = wid >> 1;      // 4 -> 64 cols each

    // grouped rasterization along M (B-tile reuse in L2)
    const int PN = gridDim.x, PM = gridDim.y;
    const int bid = blockIdx.y * PN + blockIdx.x;
    const int GM = 16;
    const int npg = GM * PN;
    const int fm  = (bid / npg) * GM;
    const int gsm = (PM - fm < GM) ? (PM - fm) : GM;
    const int pm  = fm + (bid % gsm);
    const int pn  = (bid % npg) / gsm;
    const int m0 = pm * BM;
    const int n0 = pn * BN;

    const __half* Ag = g_Xh + (size_t)m0 * KDIM;
    const __half* Bg = g_Wt + (size_t)n0 * KDIM;

    const int c8 = tid & 7;
    const int r0 = tid >> 3;          // 0..31

    float accf[4][8][4];
#pragma unroll
    for (int i = 0; i < 4; ++i)
#pragma unroll
        for (int j = 0; j < 8; ++j)
#pragma unroll
            for (int v = 0; v < 4; ++v) accf[i][j][v] = 0.f;

    const int a_r = warp_m * 64 + (lane & 15);
    const int a_c = (lane >> 4) * 8;
    const int b_r = warp_n * 64 + ((lane >> 4) * 8) + (lane & 7);
    const int b_c = ((lane >> 3) & 1) * 8;

    const int NIT = KDIM / BK;        // 64

    // prologue: stage 0
    {
        const uint32_t sa  = sbase;
        const uint32_t sbb = sbase + ATILE_B;
#pragma unroll
        for (int p = 0; p < 4; ++p) {
            const int row = r0 + p * 32;
            cp16(sa + (uint32_t)(row * ROWH + c8 * 8) * 2, Ag + (size_t)row * KDIM + c8 * 8);
        }
#pragma unroll
        for (int p = 0; p < 8; ++p) {
            const int row = r0 + p * 32;
            cp16(sbb + (uint32_t)(row * ROWH + c8 * 8) * 2, Bg + (size_t)row * KDIM + c8 * 8);
        }
        asm volatile("cp.async.commit_group;" ::: "memory");
    }

#pragma unroll 1
    for (int it = 0; it < NIT; ++it) {
        asm volatile("cp.async.wait_group 0;" ::: "memory");
        __syncthreads();

        if (it + 1 < NIT) {
            const int st = (it + 1) & 1;
            const int k0 = (it + 1) * BK;
            const uint32_t sa  = sbase + st * STAGE_B;
            const uint32_t sbb = sa + ATILE_B;
#pragma unroll
            for (int p = 0; p < 4; ++p) {
                const int row = r0 + p * 32;
                cp16(sa + (uint32_t)(row * ROWH + c8 * 8) * 2,
                     Ag + (size_t)row * KDIM + k0 + c8 * 8);
            }
#pragma unroll
            for (int p = 0; p < 8; ++p) {
                const int row = r0 + p * 32;
                cp16(sbb + (uint32_t)(row * ROWH + c8 * 8) * 2,
                     Bg + (size_t)row * KDIM + k0 + c8 * 8);
            }
        }
        asm volatile("cp.async.commit_group;" ::: "memory");

        const int st = it & 1;
        const uint32_t sa  = sbase + st * STAGE_B;
        const uint32_t sbb = sa + ATILE_B;
#pragma unroll
        for (int ks = 0; ks < 4; ++ks) {
            const int kh = ks * 16;
            uint32_t Af[4][4];
#pragma unroll
            for (int mi = 0; mi < 4; ++mi)
                ldm_x4(Af[mi], sa + (uint32_t)(((a_r + mi * 16) * ROWH) + kh + a_c) * 2);
#pragma unroll
            for (int nj = 0; nj < 4; ++nj) {
                uint32_t Bf[4];
                ldm_x4(Bf, sbb + (uint32_t)(((b_r + nj * 16) * ROWH) + kh + b_c) * 2);
#pragma unroll
                for (int mi = 0; mi < 4; ++mi) {
                    mma_f(accf[mi][2 * nj],     Af[mi], Bf[0], Bf[1]);
                    mma_f(accf[mi][2 * nj + 1], Af[mi], Bf[2], Bf[3]);
                }
            }
        }
    }

    // epilogue: bias + store
    const int r  = lane >> 2;
    const int c2 = (lane & 3) * 2;
    const int orow0 = m0 + warp_m * 64;
    const int ocol0 = n0 + warp_n * 64;
#pragma unroll
    for (int ni = 0; ni < 8; ++ni) {
        const int ncol = ocol0 + ni * 8 + c2;
        const float b0 = bias[ncol], b1 = bias[ncol + 1];
#pragma unroll
        for (int mi = 0; mi < 4; ++mi) {
            const int mrow = orow0 + mi * 16 + r;
            float2 v0 = { accf[mi][ni][0] + b0, accf[mi][ni][1] + b1 };
            float2 v1 = { accf[mi][ni][2] + b0, accf[mi][ni][3] + b1 };
            *reinterpret_cast<float2*>(out + (size_t)mrow * NDIM + ncol)       = v0;
            *reinterpret_cast<float2*>(out + (size_t)(mrow + 8) * NDIM + ncol) = v1;
        }
    }
}

// ---------------- Launch ----------------
extern "C" void kernel_launch(void* const* d_in, const int* in_sizes, int n_in,
                              void* d_out, int out_size) {
    const float* x       = (const float*)d_in[0];
    const int*   qweight = (const int*)d_in[1];
    const float* scales  = (const float*)d_in[2];
    const int*   qzeros  = (const int*)d_in[3];
    const float* bias    = (const float*)d_in[4];
    float* out = (float*)d_out;

    const long long xsz = (long long)in_sizes[0];
    const int M = (int)(xsz / KDIM);          // 8192

    const long long n8 = xsz / 8;
    const int cv_blocks = (int)((n8 + 255) / 256);
    prep_kernel<<<DQ_BLOCKS + cv_blocks, 256>>>(x, n8, qweight, scales, qzeros);

    cudaFuncSetAttribute(gemm_kernel, cudaFuncAttributeMaxDynamicSharedMemorySize, SMEM_BYTES);
    gemm_kernel<<<dim3(NDIM / BN, M / BM), 256, SMEM_BYTES>>>(bias, out);
}